// round 11
// baseline (speedup 1.0000x reference)
#include <cuda_runtime.h>
#include <math.h>

#define NPART 32
#define NT    3072                 // nodes; NT-1 linear intervals
#define T0F   (-2.99573227355399099343f)   // logf(0.05)
#define T1F   ( 3.46573590279972654709f)   // logf(32)
#define HTF   ((T1F - T0F) / (float)(NT - 1))
#define INVHT ((float)(NT - 1) / (T1F - T0F))
#define LN2F  (0.69314718055994530942f)
#define FULLM 0xffffffffu

__device__ float4 g_tab[NT];   // interval i: (v0, v1-v0, g0, g1-g0); g = (dv/dd)/d

__device__ __forceinline__ float fast_tanh(float x) {
    float ax = fabsf(x);
    float e  = __expf(ax + ax);
    float t  = 1.0f - __fdividef(2.0f, e + 1.0f);
    return copysignf(t, x);
}

// ---------------------------------------------------------------------------
// Builder: block bn computes nodes 7*bn .. 7*bn+7 (one per warp; one-node
// overlap with the next block), emits 7 packed linear intervals.
// 1st-order forward AD w.r.t. t = log d.
// ---------------------------------------------------------------------------
__global__ void __launch_bounds__(256)
build_table(const float* __restrict__ gW1, const float* __restrict__ gb1,
            const float* __restrict__ gW2, const float* __restrict__ gb2,
            const float* __restrict__ gW3, const float* __restrict__ gb3)
{
    __shared__ float sW2T[64 * 64];                  // [jj][k]
    __shared__ float sW1[192], sb1[64], sb2[64], sW3[64];
    __shared__ float4 sh[8][16], shp[8][16];
    __shared__ float2 snode[8];                      // (v, g) per warp-node
    const int tid = threadIdx.x, lane = tid & 31, wrp = tid >> 5;

    for (int idx = tid; idx < 4096; idx += 256) {
        int k = idx >> 6, jj = idx & 63;             // gW2 is [k][jj]
        sW2T[jj * 64 + k] = gW2[idx];
    }
    for (int k = tid; k < 192; k += 256) sW1[k] = gW1[k];
    for (int k = tid; k < 64; k += 256) {
        sb1[k] = gb1[k]; sb2[k] = gb2[k]; sW3[k] = gW3[k];
    }
    __syncthreads();

    const int base = blockIdx.x * 7;
    const int node = min(base + wrp, NT - 1);

    const float t  = T0F + node * HTF;
    const float d  = expf(t);
    const float f1 = d, f2 = 1.0f / d, f3 = f2 * f2;

    // phase A: layer-1 value + d/dt; lane fills k = lane, lane+32
    float* shs  = (float*)sh[wrp];
    float* shps = (float*)shp[wrp];
    #pragma unroll
    for (int q = 0; q < 2; q++) {
        int k = lane + q * 32;
        float w0 = sW1[k], w1 = sW1[64 + k], w2 = sW1[128 + k];
        float z  = sb1[k] + w0 * f1 + w1 * f2 + w2 * f3;
        float zp = w0 * f1 - w1 * f2 - 2.0f * w2 * f3;
        float h  = fast_tanh(z);
        shs[k]  = h;
        shps[k] = (1.0f - h * h) * zp;
    }
    __syncwarp();

    // phase B: lane owns rows jj = lane, lane+32
    const float4* wra = (const float4*)(&sW2T[lane * 64]);
    const float4* wrb = (const float4*)(&sW2T[(lane + 32) * 64]);
    float za = sb2[lane],      zap = 0.f;
    float zb = sb2[lane + 32], zbp = 0.f;
    #pragma unroll
    for (int r = 0; r < 16; r++) {
        int rr = (r + lane) & 15;
        float4 h4 = sh[wrp][rr];
        float4 p4 = shp[wrp][rr];
        float4 wa = wra[rr];
        float4 wb = wrb[rr];
        za  = fmaf(wa.x, h4.x, fmaf(wa.y, h4.y, fmaf(wa.z, h4.z, fmaf(wa.w, h4.w, za))));
        zap = fmaf(wa.x, p4.x, fmaf(wa.y, p4.y, fmaf(wa.z, p4.z, fmaf(wa.w, p4.w, zap))));
        zb  = fmaf(wb.x, h4.x, fmaf(wb.y, h4.y, fmaf(wb.z, h4.z, fmaf(wb.w, h4.w, zb))));
        zbp = fmaf(wb.x, p4.x, fmaf(wb.y, p4.y, fmaf(wb.z, p4.z, fmaf(wb.w, p4.w, zbp))));
    }

    float ta = fast_tanh(za), tb = fast_tanh(zb);
    float w3a = sW3[lane], w3b = sW3[lane + 32];
    float va  = fmaf(w3a, ta, w3b * tb);
    float vpa = fmaf(w3a * (1.0f - ta * ta), zap,
                     w3b * (1.0f - tb * tb) * zbp);

    #pragma unroll
    for (int off = 16; off; off >>= 1) {
        va  += __shfl_xor_sync(FULLM, va,  off);
        vpa += __shfl_xor_sync(FULLM, vpa, off);
    }
    if (lane == 0) {
        float v = va + gb3[0];
        float g = vpa * f3;                  // (dv/dt)·e^{-2t} = (dv/dd)/d
        snode[wrp] = make_float2(v, g);
    }
    __syncthreads();

    if (tid < 7) {
        int m = base + tid;
        if (m < NT - 1) {
            float2 n0 = snode[tid], n1 = snode[tid + 1];
            g_tab[m] = make_float4(n0.x, n1.x - n0.x, n0.y, n1.y - n0.y);
        }
    }
}

// ---------------------------------------------------------------------------
// Forces: persistent blocks; one warp per batch; lane l evaluates all 31
// partners. One packed LDS.128 per pair (linear interp of v and g).
// ---------------------------------------------------------------------------
__device__ __forceinline__ void pair_eval(
    int k, int lane, float px, float py, float pz,
    const float4* __restrict__ stab, float KL, float C0,
    float& fx, float& fy, float& fz, float& vacc)
{
    const int src = (lane + k) & 31;
    float qx = __shfl_sync(FULLM, px, src);
    float qy = __shfl_sync(FULLM, py, src);
    float qz = __shfl_sync(FULLM, pz, src);
    float rx = px - qx, ry = py - qy, rz = pz - qz;
    float d2 = fmaf(rx, rx, fmaf(ry, ry, rz * rz));

    float u = fmaf(__log2f(d2), KL, C0);
    u = fminf(fmaxf(u, 0.0f), (float)(NT - 1) - 0.001f);
    int   i0 = (int)u;
    float s  = u - (float)i0;

    float4 c = stab[i0];
    float v = fmaf(s, c.y, c.x);
    float g = fmaf(s, c.w, c.z);

    g = (d2 > 0.0025f) ? g : 0.0f;   // clipped: zero force

    fx = fmaf(-g, rx, fx);
    fy = fmaf(-g, ry, fy);
    fz = fmaf(-g, rz, fz);
    vacc += v;
}

#define TPB_F 384
#define GRID_F 296

__global__ void __launch_bounds__(TPB_F)
forces_kernel(const float* __restrict__ gpos, float* __restrict__ out, int B)
{
    __shared__ float4 stab[NT];        // 48 KB
    const int tid  = threadIdx.x;
    const int lane = tid & 31;
    const int wrp  = tid >> 5;

    #pragma unroll
    for (int q = 0; q < NT / TPB_F; q++)
        stab[q * TPB_F + tid] = __ldg(&g_tab[q * TPB_F + tid]);
    __syncthreads();

    const float KL = 0.5f * LN2F * INVHT;   // u = (0.5*ln(d2) - T0) * INVHT
    const float C0 = -T0F * INVHT;
    const int   WPB = TPB_F / 32;

    for (int b = blockIdx.x * WPB + wrp; b < B; b += GRID_F * WPB) {
        float px = gpos[b * 96 + lane * 3 + 0];
        float py = gpos[b * 96 + lane * 3 + 1];
        float pz = gpos[b * 96 + lane * 3 + 2];

        float fx0 = 0.f, fy0 = 0.f, fz0 = 0.f, v0 = 0.f;
        float fx1 = 0.f, fy1 = 0.f, fz1 = 0.f, v1 = 0.f;

        #pragma unroll
        for (int k = 1; k <= 29; k += 2) {
            pair_eval(k,     lane, px, py, pz, stab, KL, C0, fx0, fy0, fz0, v0);
            pair_eval(k + 1, lane, px, py, pz, stab, KL, C0, fx1, fy1, fz1, v1);
        }
        pair_eval(31, lane, px, py, pz, stab, KL, C0, fx0, fy0, fz0, v0);

        out[b * 96 + lane * 3 + 0] = fx0 + fx1;
        out[b * 96 + lane * 3 + 1] = fy0 + fy1;
        out[b * 96 + lane * 3 + 2] = fz0 + fz1;

        float vloc = v0 + v1;              // every pair counted twice
        #pragma unroll
        for (int off = 16; off; off >>= 1)
            vloc += __shfl_xor_sync(FULLM, vloc, off);
        if (lane == 0)
            out[(long long)B * 96 + b] = 0.5f * vloc;
    }
}

extern "C" void kernel_launch(void* const* d_in, const int* in_sizes, int n_in,
                              void* d_out, int out_size)
{
    const float* pos = (const float*)d_in[0];
    const float* W1  = (const float*)d_in[1];
    const float* b1  = (const float*)d_in[2];
    const float* W2  = (const float*)d_in[3];
    const float* b2  = (const float*)d_in[4];
    const float* W3  = (const float*)d_in[5];
    const float* b3  = (const float*)d_in[6];
    float* out = (float*)d_out;
    const int B = in_sizes[0] / 96;

    build_table<<<(NT - 1 + 6) / 7, 256>>>(W1, b1, W2, b2, W3, b3);
    forces_kernel<<<GRID_F, TPB_F>>>(pos, out, B);
}

// round 12
// speedup vs baseline: 1.1553x; 1.1553x over previous
#include <cuda_runtime.h>
#include <math.h>

#define NPART 32
#define NT    3072                 // nodes; NT-1 linear intervals
#define T0F   (-2.99573227355399099343f)   // logf(0.05)
#define T1F   ( 3.46573590279972654709f)   // logf(32)
#define HTF   ((T1F - T0F) / (float)(NT - 1))
#define INVHT ((float)(NT - 1) / (T1F - T0F))
#define LN2F  (0.69314718055994530942f)
#define FULLM 0xffffffffu

__device__ float4 g_tab[NT];   // interval i: (v0, v1-v0, g0, g1-g0); g = (dv/dd)/d

__device__ __forceinline__ float fast_tanh(float x) {
    float ax = fabsf(x);
    float e  = __expf(ax + ax);
    float t  = 1.0f - __fdividef(2.0f, e + 1.0f);
    return copysignf(t, x);
}

// ---------------------------------------------------------------------------
// Builder: block bn computes nodes 7*bn .. 7*bn+7 (one per warp; one-node
// overlap with the next block), emits 7 packed linear intervals.
// 1st-order forward AD w.r.t. t = log d. Conflict-free smem throughout:
// W2 kept [k][jj] (no transpose); lane reads stride-1 columns.
// ---------------------------------------------------------------------------
__global__ void __launch_bounds__(256)
build_table(const float* __restrict__ gW1, const float* __restrict__ gb1,
            const float* __restrict__ gW2, const float* __restrict__ gb2,
            const float* __restrict__ gW3, const float* __restrict__ gb3)
{
    __shared__ float sW2[64 * 64];                   // [k][jj], as in gmem
    __shared__ float sW1[192], sb1[64], sb2[64], sW3[64];
    __shared__ float4 sh[8][16], shp[8][16];         // per-warp h, h' (as float4)
    __shared__ float2 snode[8];                      // (v, g) per warp-node
    const int tid = threadIdx.x, lane = tid & 31, wrp = tid >> 5;

    for (int idx = tid; idx < 4096; idx += 256)
        sW2[idx] = gW2[idx];                          // coalesced, conflict-free
    for (int k = tid; k < 192; k += 256) sW1[k] = gW1[k];
    for (int k = tid; k < 64; k += 256) {
        sb1[k] = gb1[k]; sb2[k] = gb2[k]; sW3[k] = gW3[k];
    }
    __syncthreads();

    const int base = blockIdx.x * 7;
    const int node = min(base + wrp, NT - 1);

    const float t  = T0F + node * HTF;
    const float d  = expf(t);
    const float f1 = d, f2 = 1.0f / d, f3 = f2 * f2;

    // phase A: layer-1 value + d/dt; lane fills k = lane, lane+32
    float* shs  = (float*)sh[wrp];
    float* shps = (float*)shp[wrp];
    #pragma unroll
    for (int q = 0; q < 2; q++) {
        int k = lane + q * 32;
        float w0 = sW1[k], w1 = sW1[64 + k], w2 = sW1[128 + k];
        float z  = sb1[k] + w0 * f1 + w1 * f2 + w2 * f3;
        float zp = w0 * f1 - w1 * f2 - 2.0f * w2 * f3;
        float h  = fast_tanh(z);
        shs[k]  = h;
        shps[k] = (1.0f - h * h) * zp;
    }
    __syncwarp();

    // phase B: lane owns output units jj = lane, lane+32.
    // sW2 reads are stride-1 across lanes (1 phase); h/h' are broadcasts.
    float za = sb2[lane],      zap = 0.f;
    float zb = sb2[lane + 32], zbp = 0.f;
    #pragma unroll
    for (int r = 0; r < 16; r++) {
        float4 h4 = sh[wrp][r];
        float4 p4 = shp[wrp][r];
        float hc[4] = {h4.x, h4.y, h4.z, h4.w};
        float pc[4] = {p4.x, p4.y, p4.z, p4.w};
        #pragma unroll
        for (int c = 0; c < 4; c++) {
            int k = 4 * r + c;
            float wA = sW2[k * 64 + lane];
            float wB = sW2[k * 64 + lane + 32];
            za  = fmaf(wA, hc[c], za);
            zap = fmaf(wA, pc[c], zap);
            zb  = fmaf(wB, hc[c], zb);
            zbp = fmaf(wB, pc[c], zbp);
        }
    }

    float ta = fast_tanh(za), tb = fast_tanh(zb);
    float w3a = sW3[lane], w3b = sW3[lane + 32];
    float va  = fmaf(w3a, ta, w3b * tb);
    float vpa = fmaf(w3a * (1.0f - ta * ta), zap,
                     w3b * (1.0f - tb * tb) * zbp);

    #pragma unroll
    for (int off = 16; off; off >>= 1) {
        va  += __shfl_xor_sync(FULLM, va,  off);
        vpa += __shfl_xor_sync(FULLM, vpa, off);
    }
    if (lane == 0) {
        float v = va + gb3[0];
        float g = vpa * f3;                  // (dv/dt)·e^{-2t} = (dv/dd)/d
        snode[wrp] = make_float2(v, g);
    }
    __syncthreads();

    if (tid < 7) {
        int m = base + tid;
        if (m < NT - 1) {
            float2 n0 = snode[tid], n1 = snode[tid + 1];
            g_tab[m] = make_float4(n0.x, n1.x - n0.x, n0.y, n1.y - n0.y);
        }
    }
}

// ---------------------------------------------------------------------------
// Forces: 2 warps per batch (k=1..15 / 16..31), both-sides scheme (no
// reaction shuffles). Table gathered via __ldg (L1-resident, 48 KB).
// ---------------------------------------------------------------------------
__device__ __forceinline__ void pair_eval(
    int k, int lane, float px, float py, float pz,
    float KL, float C0,
    float& fx, float& fy, float& fz, float& vacc)
{
    const int src = (lane + k) & 31;
    float qx = __shfl_sync(FULLM, px, src);
    float qy = __shfl_sync(FULLM, py, src);
    float qz = __shfl_sync(FULLM, pz, src);
    float rx = px - qx, ry = py - qy, rz = pz - qz;
    float d2 = fmaf(rx, rx, fmaf(ry, ry, rz * rz));

    float u = fmaf(__log2f(d2), KL, C0);
    u = fminf(fmaxf(u, 0.0f), (float)(NT - 1) - 0.001f);
    int   i0 = (int)u;
    float s  = u - (float)i0;

    float4 c = __ldg(&g_tab[i0]);
    float v = fmaf(s, c.y, c.x);
    float g = fmaf(s, c.w, c.z);

    g = (d2 > 0.0025f) ? g : 0.0f;   // clipped: zero force

    fx = fmaf(-g, rx, fx);
    fy = fmaf(-g, ry, fy);
    fz = fmaf(-g, rz, fz);
    vacc += v;
}

#define TPB_F 256

__global__ void __launch_bounds__(TPB_F)
forces_kernel(const float* __restrict__ gpos, float* __restrict__ out, int B)
{
    __shared__ float4 sF[TPB_F / 32][NPART];
    __shared__ float  sV[TPB_F / 32];
    const int tid  = threadIdx.x;
    const int lane = tid & 31;
    const int wrp  = tid >> 5;
    const int bq   = blockIdx.x * (TPB_F / 64) + (wrp >> 1);
    const int half = wrp & 1;            // 0: k=1..15, 1: k=16..31

    float px = 0.f, py = 0.f, pz = 0.f;
    if (bq < B) {
        px = gpos[bq * 96 + lane * 3 + 0];
        py = gpos[bq * 96 + lane * 3 + 1];
        pz = gpos[bq * 96 + lane * 3 + 2];
    }

    const float KL = 0.5f * LN2F * INVHT;   // u = (0.5*ln(d2) - T0) * INVHT
    const float C0 = -T0F * INVHT;

    float fx0 = 0.f, fy0 = 0.f, fz0 = 0.f, v0 = 0.f;
    float fx1 = 0.f, fy1 = 0.f, fz1 = 0.f, v1 = 0.f;

    if (half == 0) {
        #pragma unroll
        for (int k = 1; k <= 14; k += 2) {
            pair_eval(k,     lane, px, py, pz, KL, C0, fx0, fy0, fz0, v0);
            pair_eval(k + 1, lane, px, py, pz, KL, C0, fx1, fy1, fz1, v1);
        }
        pair_eval(15, lane, px, py, pz, KL, C0, fx0, fy0, fz0, v0);
    } else {
        #pragma unroll
        for (int k = 16; k <= 30; k += 2) {
            pair_eval(k,     lane, px, py, pz, KL, C0, fx0, fy0, fz0, v0);
            pair_eval(k + 1, lane, px, py, pz, KL, C0, fx1, fy1, fz1, v1);
        }
    }

    sF[wrp][lane] = make_float4(fx0 + fx1, fy0 + fy1, fz0 + fz1, 0.f);
    float vloc = v0 + v1;
    #pragma unroll
    for (int off = 16; off; off >>= 1)
        vloc += __shfl_xor_sync(FULLM, vloc, off);
    if (lane == 0) sV[wrp] = vloc;
    __syncthreads();

    if (half == 0 && bq < B) {
        float4 a = sF[wrp][lane];
        float4 c = sF[wrp + 1][lane];
        out[bq * 96 + lane * 3 + 0] = a.x + c.x;
        out[bq * 96 + lane * 3 + 1] = a.y + c.y;
        out[bq * 96 + lane * 3 + 2] = a.z + c.z;
        if (lane == 0)    // every ordered pair counted once -> V = 0.5 * sum
            out[(long long)B * 96 + bq] = 0.5f * (sV[wrp] + sV[wrp + 1]);
    }
}

extern "C" void kernel_launch(void* const* d_in, const int* in_sizes, int n_in,
                              void* d_out, int out_size)
{
    const float* pos = (const float*)d_in[0];
    const float* W1  = (const float*)d_in[1];
    const float* b1  = (const float*)d_in[2];
    const float* W2  = (const float*)d_in[3];
    const float* b2  = (const float*)d_in[4];
    const float* W3  = (const float*)d_in[5];
    const float* b3  = (const float*)d_in[6];
    float* out = (float*)d_out;
    const int B = in_sizes[0] / 96;
    const int bpb = TPB_F / 64;   // batches per block

    build_table<<<(NT - 1 + 6) / 7, 256>>>(W1, b1, W2, b2, W3, b3);
    forces_kernel<<<(B + bpb - 1) / bpb, TPB_F>>>(pos, out, B);
}

// round 13
// speedup vs baseline: 1.3016x; 1.1266x over previous
#include <cuda_runtime.h>
#include <math.h>

#define NPART 32
#define NT    1024                 // nodes; NT-1 linear intervals
#define T0F   (-2.99573227355399099343f)   // logf(0.05)
#define T1F   ( 3.46573590279972654709f)   // logf(32)
#define HTF   ((T1F - T0F) / (float)(NT - 1))
#define INVHT ((float)(NT - 1) / (T1F - T0F))
#define LN2F  (0.69314718055994530942f)
#define FULLM 0xffffffffu

__device__ float4 g_tab[NT];   // interval i: (v0, v1-v0, g0, g1-g0); g = (dv/dd)/d

__device__ __forceinline__ float fast_tanh(float x) {
    float ax = fabsf(x);
    float e  = __expf(ax + ax);
    float t  = 1.0f - __fdividef(2.0f, e + 1.0f);
    return copysignf(t, x);
}

// ---------------------------------------------------------------------------
// Builder: block bn computes nodes 7*bn .. 7*bn+7 (one per warp; one-node
// overlap with the next block), emits 7 packed linear intervals.
// 1st-order forward AD w.r.t. t = log d. Conflict-free smem: W2 kept [k][jj],
// lane reads stride-1 columns; h/h' broadcast.
// ---------------------------------------------------------------------------
__global__ void __launch_bounds__(256)
build_table(const float* __restrict__ gW1, const float* __restrict__ gb1,
            const float* __restrict__ gW2, const float* __restrict__ gb2,
            const float* __restrict__ gW3, const float* __restrict__ gb3)
{
    __shared__ float sW2[64 * 64];                   // [k][jj], as in gmem
    __shared__ float sW1[192], sb1[64], sb2[64], sW3[64];
    __shared__ float4 sh[8][16], shp[8][16];         // per-warp h, h' (as float4)
    __shared__ float2 snode[8];                      // (v, g) per warp-node
    const int tid = threadIdx.x, lane = tid & 31, wrp = tid >> 5;

    for (int idx = tid; idx < 4096; idx += 256)
        sW2[idx] = gW2[idx];                          // coalesced, conflict-free
    for (int k = tid; k < 192; k += 256) sW1[k] = gW1[k];
    for (int k = tid; k < 64; k += 256) {
        sb1[k] = gb1[k]; sb2[k] = gb2[k]; sW3[k] = gW3[k];
    }
    __syncthreads();

    const int base = blockIdx.x * 7;
    const int node = min(base + wrp, NT - 1);

    const float t  = T0F + node * HTF;
    const float d  = expf(t);
    const float f1 = d, f2 = 1.0f / d, f3 = f2 * f2;

    // phase A: layer-1 value + d/dt; lane fills k = lane, lane+32
    float* shs  = (float*)sh[wrp];
    float* shps = (float*)shp[wrp];
    #pragma unroll
    for (int q = 0; q < 2; q++) {
        int k = lane + q * 32;
        float w0 = sW1[k], w1 = sW1[64 + k], w2 = sW1[128 + k];
        float z  = sb1[k] + w0 * f1 + w1 * f2 + w2 * f3;
        float zp = w0 * f1 - w1 * f2 - 2.0f * w2 * f3;
        float h  = fast_tanh(z);
        shs[k]  = h;
        shps[k] = (1.0f - h * h) * zp;
    }
    __syncwarp();

    // phase B: lane owns output units jj = lane, lane+32
    float za = sb2[lane],      zap = 0.f;
    float zb = sb2[lane + 32], zbp = 0.f;
    #pragma unroll
    for (int r = 0; r < 16; r++) {
        float4 h4 = sh[wrp][r];
        float4 p4 = shp[wrp][r];
        float hc[4] = {h4.x, h4.y, h4.z, h4.w};
        float pc[4] = {p4.x, p4.y, p4.z, p4.w};
        #pragma unroll
        for (int c = 0; c < 4; c++) {
            int k = 4 * r + c;
            float wA = sW2[k * 64 + lane];
            float wB = sW2[k * 64 + lane + 32];
            za  = fmaf(wA, hc[c], za);
            zap = fmaf(wA, pc[c], zap);
            zb  = fmaf(wB, hc[c], zb);
            zbp = fmaf(wB, pc[c], zbp);
        }
    }

    float ta = fast_tanh(za), tb = fast_tanh(zb);
    float w3a = sW3[lane], w3b = sW3[lane + 32];
    float va  = fmaf(w3a, ta, w3b * tb);
    float vpa = fmaf(w3a * (1.0f - ta * ta), zap,
                     w3b * (1.0f - tb * tb) * zbp);

    #pragma unroll
    for (int off = 16; off; off >>= 1) {
        va  += __shfl_xor_sync(FULLM, va,  off);
        vpa += __shfl_xor_sync(FULLM, vpa, off);
    }
    if (lane == 0) {
        float v = va + gb3[0];
        float g = vpa * f3;                  // (dv/dt)·e^{-2t} = (dv/dd)/d
        snode[wrp] = make_float2(v, g);
    }
    __syncthreads();

    if (tid < 7) {
        int m = base + tid;
        if (m < NT - 1) {
            float2 n0 = snode[tid], n1 = snode[tid + 1];
            g_tab[m] = make_float4(n0.x, n1.x - n0.x, n0.y, n1.y - n0.y);
        }
    }
}

// ---------------------------------------------------------------------------
// Forces: smem table (16 KB -> thread-capped occupancy), 2 warps per batch
// (k=1..15 / 16..31, both-sides: no reaction shuffles), smem combine.
// ---------------------------------------------------------------------------
__device__ __forceinline__ void pair_eval(
    int k, int lane, float px, float py, float pz,
    const float4* __restrict__ stab, float KL, float C0,
    float& fx, float& fy, float& fz, float& vacc)
{
    const int src = (lane + k) & 31;
    float qx = __shfl_sync(FULLM, px, src);
    float qy = __shfl_sync(FULLM, py, src);
    float qz = __shfl_sync(FULLM, pz, src);
    float rx = px - qx, ry = py - qy, rz = pz - qz;
    float d2 = fmaf(rx, rx, fmaf(ry, ry, rz * rz));

    float u = fmaf(__log2f(d2), KL, C0);
    u = fminf(fmaxf(u, 0.0f), (float)(NT - 1) - 0.001f);
    int   i0 = (int)u;
    float s  = u - (float)i0;

    float4 c = stab[i0];
    float v = fmaf(s, c.y, c.x);
    float g = fmaf(s, c.w, c.z);

    g = (d2 > 0.0025f) ? g : 0.0f;   // clipped: zero force

    fx = fmaf(-g, rx, fx);
    fy = fmaf(-g, ry, fy);
    fz = fmaf(-g, rz, fz);
    vacc += v;
}

#define TPB_F 256

__global__ void __launch_bounds__(TPB_F)
forces_kernel(const float* __restrict__ gpos, float* __restrict__ out, int B)
{
    __shared__ float4 stab[NT];               // 16 KB
    __shared__ float4 sF[TPB_F / 32][NPART];
    __shared__ float  sV[TPB_F / 32];
    const int tid  = threadIdx.x;
    const int lane = tid & 31;
    const int wrp  = tid >> 5;
    const int bq   = blockIdx.x * (TPB_F / 64) + (wrp >> 1);
    const int half = wrp & 1;                 // 0: k=1..15, 1: k=16..31

    #pragma unroll
    for (int q = 0; q < NT / TPB_F; q++)
        stab[q * TPB_F + tid] = __ldg(&g_tab[q * TPB_F + tid]);

    float px = 0.f, py = 0.f, pz = 0.f;
    if (bq < B) {
        px = gpos[bq * 96 + lane * 3 + 0];
        py = gpos[bq * 96 + lane * 3 + 1];
        pz = gpos[bq * 96 + lane * 3 + 2];
    }
    __syncthreads();

    const float KL = 0.5f * LN2F * INVHT;     // u = (0.5*ln(d2) - T0) * INVHT
    const float C0 = -T0F * INVHT;

    float fx0 = 0.f, fy0 = 0.f, fz0 = 0.f, v0 = 0.f;
    float fx1 = 0.f, fy1 = 0.f, fz1 = 0.f, v1 = 0.f;

    if (half == 0) {
        #pragma unroll
        for (int k = 1; k <= 14; k += 2) {
            pair_eval(k,     lane, px, py, pz, stab, KL, C0, fx0, fy0, fz0, v0);
            pair_eval(k + 1, lane, px, py, pz, stab, KL, C0, fx1, fy1, fz1, v1);
        }
        pair_eval(15, lane, px, py, pz, stab, KL, C0, fx0, fy0, fz0, v0);
    } else {
        #pragma unroll
        for (int k = 16; k <= 30; k += 2) {
            pair_eval(k,     lane, px, py, pz, stab, KL, C0, fx0, fy0, fz0, v0);
            pair_eval(k + 1, lane, px, py, pz, stab, KL, C0, fx1, fy1, fz1, v1);
        }
    }

    sF[wrp][lane] = make_float4(fx0 + fx1, fy0 + fy1, fz0 + fz1, 0.f);
    float vloc = v0 + v1;
    #pragma unroll
    for (int off = 16; off; off >>= 1)
        vloc += __shfl_xor_sync(FULLM, vloc, off);
    if (lane == 0) sV[wrp] = vloc;
    __syncthreads();

    if (half == 0 && bq < B) {
        float4 a = sF[wrp][lane];
        float4 c = sF[wrp + 1][lane];
        out[bq * 96 + lane * 3 + 0] = a.x + c.x;
        out[bq * 96 + lane * 3 + 1] = a.y + c.y;
        out[bq * 96 + lane * 3 + 2] = a.z + c.z;
        if (lane == 0)    // every ordered pair counted once -> V = 0.5 * sum
            out[(long long)B * 96 + bq] = 0.5f * (sV[wrp] + sV[wrp + 1]);
    }
}

extern "C" void kernel_launch(void* const* d_in, const int* in_sizes, int n_in,
                              void* d_out, int out_size)
{
    const float* pos = (const float*)d_in[0];
    const float* W1  = (const float*)d_in[1];
    const float* b1  = (const float*)d_in[2];
    const float* W2  = (const float*)d_in[3];
    const float* b2  = (const float*)d_in[4];
    const float* W3  = (const float*)d_in[5];
    const float* b3  = (const float*)d_in[6];
    float* out = (float*)d_out;
    const int B = in_sizes[0] / 96;
    const int bpb = TPB_F / 64;   // batches per block

    build_table<<<(NT - 1 + 6) / 7, 256>>>(W1, b1, W2, b2, W3, b3);
    forces_kernel<<<(B + bpb - 1) / bpb, TPB_F>>>(pos, out, B);
}